// round 13
// baseline (speedup 1.0000x reference)
#include <cuda_runtime.h>
#include <cuda_fp16.h>
#include <cstdint>
#include <cstddef>

#define NB 1024
#define NT 512
#define NH 128
#define BT (NB * NT)
#define NBC 14   // batches per cluster (one m16 tile, 2 pad rows)

// ---------------- scratch (device globals; no runtime allocation) ----------------
__device__ __half g_h0[(size_t)NB * NT * NH];   // layer0 out fp16 [B][T][H]
__device__ __half g_h1[(size_t)NB * NT * NH];   // layer1 out fp16 [B][T][H]
__device__ float  g_hlast[NB * NH];             // layer2 last h (fp32)
__device__ __half g_xph[(size_t)BT * 512];      // x-projection fp16 (reused per layer)
__device__ __half g_WF[2][65536];               // mma frag-packed w_ih (layers 1,2)
__device__ __half g_WR[3][65536];               // mma frag-packed w_hh (all layers)
__device__ float  g_biasxp[3][512];             // per-layer bias (c = u*4+q order)
__device__ float  g_w0p[512 * 8];               // layer0 w_ih packed [c][8] (k<6)

// ---------------- activations / helpers ----------------
__device__ __forceinline__ float fast_tanh(float x) {
    float y;
    asm("tanh.approx.f32 %0, %1;" : "=f"(y) : "f"(x));
    return y;
}
__device__ __forceinline__ float fast_sig(float x) {
    return fmaf(0.5f, fast_tanh(0.5f * x), 0.5f);
}
__device__ __forceinline__ uint32_t smem_u32(const void* p) {
    uint32_t a;
    asm("{ .reg .u64 t; cvta.to.shared.u64 t, %1; cvt.u32.u64 %0, t; }" : "=r"(a) : "l"(p));
    return a;
}
// store one b16 into the PEER CTA's shared memory (cluster DSMEM)
__device__ __forceinline__ void st_peer_b16(uint32_t laddr, uint32_t peer_rank, __half v) {
    unsigned short s = __half_as_ushort(v);
    asm volatile("{\n\t.reg .b32 r;\n\t"
                 "mapa.shared::cluster.u32 r, %0, %1;\n\t"
                 "st.shared::cluster.b16 [r], %2;\n\t}"
                 :: "r"(laddr), "r"(peer_rank), "h"(s) : "memory");
}
#define CLUSTER_ARRIVE() asm volatile("barrier.cluster.arrive.aligned;" ::: "memory")
#define CLUSTER_WAIT()   asm volatile("barrier.cluster.wait.aligned;" ::: "memory")

// ---------------- prep: mma B-frag pack for a [512,128] matrix + bias ----------
__global__ void prep_mma_kernel(const float* __restrict__ W,
                                const float* __restrict__ b_ih,
                                const float* __restrict__ b_hh,
                                __half* __restrict__ WF, float* __restrict__ bias)
{
    for (int idx = blockIdx.x * blockDim.x + threadIdx.x; idx < 65536;
         idx += gridDim.x * blockDim.x) {
        int h4   = idx & 3;
        int lane = (idx >> 2) & 31;
        int ks   = (idx >> 7) & 7;
        int cb   = idx >> 10;
        int c = cb * 8 + (lane >> 2);
        int q = c & 3, u = c >> 2;
        int g = q * NH + u;
        int k = ks * 16 + (lane & 3) * 2 + (h4 & 1) + (h4 >> 1) * 8;
        WF[idx] = __float2half(W[g * NH + k]);
    }
    for (int c = blockIdx.x * blockDim.x + threadIdx.x; c < 512;
         c += gridDim.x * blockDim.x) {
        int q = c & 3, u = c >> 2;
        int g = q * NH + u;
        bias[c] = b_ih[g] + b_hh[g];
    }
}

// ---------------- prep: layer0 w_ih pack (K=6) + bias ----------------
__global__ void prep_l0_kernel(const float* __restrict__ w_ih,
                               const float* __restrict__ b_ih,
                               const float* __restrict__ b_hh,
                               float* __restrict__ w0p, float* __restrict__ bias)
{
    for (int idx = blockIdx.x * blockDim.x + threadIdx.x; idx < 512 * 8;
         idx += gridDim.x * blockDim.x) {
        int k = idx & 7, c = idx >> 3;
        int q = c & 3, u = c >> 2;
        int g = q * NH + u;
        w0p[idx] = (k < 6) ? w_ih[g * 6 + k] : 0.0f;
    }
    for (int c = blockIdx.x * blockDim.x + threadIdx.x; c < 512;
         c += gridDim.x * blockDim.x) {
        int q = c & 3, u = c >> 2;
        int g = q * NH + u;
        bias[c] = b_ih[g] + b_hh[g];
    }
}

// ---------------- layer0 x-projection (scalar, K=6) -> fp16 ----------------
__global__ void __launch_bounds__(512, 1)
xp0_kernel(const float* __restrict__ x, const float* __restrict__ w0p,
           const float* __restrict__ bias, __half* __restrict__ XP)
{
    __shared__ __align__(16) float xs[128 * 8];
    const int tid = threadIdx.x;
    const size_t row0 = (size_t)blockIdx.x * 128;

    for (int i = tid; i < 1024; i += 512) {
        int r = i >> 3, k = i & 7;
        xs[i] = (k < 6) ? x[(row0 + r) * 6 + k] : 0.0f;
    }
    __syncthreads();

    const int c = tid;
    float4 w01 = *reinterpret_cast<const float4*>(&w0p[c * 8]);
    float4 w23 = *reinterpret_cast<const float4*>(&w0p[c * 8 + 4]);
    float bc = bias[c];
    for (int r = 0; r < 128; ++r) {
        float4 x01 = *reinterpret_cast<const float4*>(&xs[r * 8]);
        float2 x2  = *reinterpret_cast<const float2*>(&xs[r * 8 + 4]);
        float s = bc;
        s = fmaf(w01.x, x01.x, s);
        s = fmaf(w01.y, x01.y, s);
        s = fmaf(w01.z, x01.z, s);
        s = fmaf(w01.w, x01.w, s);
        s = fmaf(w23.x, x2.x, s);
        s = fmaf(w23.y, x2.y, s);
        XP[(row0 + r) * 512 + c] = __float2half(s);
    }
}

// ---------------- layers 1,2 x-projection via mma.sync -> fp16 ----------------
__global__ void __launch_bounds__(512, 1)
xp_mma_kernel(const __half* __restrict__ X, const __half* __restrict__ WF,
              const float* __restrict__ bias, __half* __restrict__ XP)
{
    __shared__ __align__(16) __half xs[128 * 136];
    const int tid  = threadIdx.x;
    const int wid  = tid >> 5;
    const int lane = tid & 31;
    const size_t row0 = (size_t)blockIdx.x * 128;
    const int ny = blockIdx.y;

    for (int i = tid; i < 2048; i += 512) {
        int r = i >> 4, cvec = i & 15;
        reinterpret_cast<uint4*>(xs)[r * 17 + cvec] =
            reinterpret_cast<const uint4*>(X + (row0 + r) * NH)[cvec];
    }
    __syncthreads();

    const int wm = wid & 3;
    const int wn = wid >> 2;
    const int cb0 = ny * 32 + wn * 8;
    const uint2* __restrict__ WFp = reinterpret_cast<const uint2*>(WF);

    const int lrow = (lane & 7) + ((lane >> 3) & 1) * 8;
    const int kadd = (lane >> 4) * 8;
    const uint32_t xsb = smem_u32(xs);

    float acc[2][8][4];
#pragma unroll
    for (int mt = 0; mt < 2; ++mt)
#pragma unroll
        for (int nt = 0; nt < 8; ++nt)
#pragma unroll
            for (int i = 0; i < 4; ++i) acc[mt][nt][i] = 0.0f;

#pragma unroll
    for (int ks = 0; ks < 8; ++ks) {
        uint2 b[8];
#pragma unroll
        for (int nt = 0; nt < 8; ++nt)
            b[nt] = WFp[(size_t)((cb0 + nt) * 8 + ks) * 32 + lane];

#pragma unroll
        for (int mt = 0; mt < 2; ++mt) {
            int row = wm * 32 + mt * 16 + lrow;
            uint32_t addr = xsb + (uint32_t)(row * 136 + ks * 16 + kadd) * 2;
            uint32_t a0, a1, a2, a3;
            asm volatile("ldmatrix.sync.aligned.m8n8.x4.shared.b16 {%0,%1,%2,%3}, [%4];"
                         : "=r"(a0), "=r"(a1), "=r"(a2), "=r"(a3) : "r"(addr));
#pragma unroll
            for (int nt = 0; nt < 8; ++nt) {
                asm volatile(
                    "mma.sync.aligned.m16n8k16.row.col.f32.f16.f16.f32 "
                    "{%0,%1,%2,%3}, {%4,%5,%6,%7}, {%8,%9}, {%0,%1,%2,%3};"
                    : "+f"(acc[mt][nt][0]), "+f"(acc[mt][nt][1]),
                      "+f"(acc[mt][nt][2]), "+f"(acc[mt][nt][3])
                    : "r"(a0), "r"(a1), "r"(a2), "r"(a3),
                      "r"(b[nt].x), "r"(b[nt].y));
            }
        }
    }

    const int gp = lane >> 2, tig = lane & 3;
#pragma unroll
    for (int mt = 0; mt < 2; ++mt) {
#pragma unroll
        for (int nt = 0; nt < 8; ++nt) {
            size_t row = row0 + wm * 32 + mt * 16 + gp;
            int col = ny * 256 + wn * 64 + nt * 8 + tig * 2;
            float2 bb = *reinterpret_cast<const float2*>(&bias[col]);
            __half2 o0 = __floats2half2_rn(acc[mt][nt][0] + bb.x, acc[mt][nt][1] + bb.y);
            __half2 o1 = __floats2half2_rn(acc[mt][nt][2] + bb.x, acc[mt][nt][3] + bb.y);
            *reinterpret_cast<__half2*>(&XP[row * 512 + col]) = o0;
            *reinterpret_cast<__half2*>(&XP[(row + 8) * 512 + col]) = o1;
        }
    }
}

// ---------------- recurrent LSTM layer: 2-CTA cluster, N-split ----------------
// 74 clusters x 2 CTAs = 148 CTAs; cluster = 14 batches (one m16 tile).
// CTA rank r computes gate cols [256r, 256r+256): warp owns 2 n8 tiles
// -> 8 ldmatrix.x4 + 16 mma (f16 acc) per warp per step. Each CTA's 64 h
// units are written into BOTH CTAs' double-buffered A tiles (local STS +
// peer DSMEM st); barrier.cluster arrive/wait with xp(t+1) prefetch between.
__global__ void __launch_bounds__(512, 1) __cluster_dims__(2, 1, 1)
rec_mma_kernel(const __half* __restrict__ xp,     // [BT][512] fp16, bias included
               const __half* __restrict__ WR,     // frag-packed w_hh
               __half* __restrict__ hout,         // [B][T][128] or nullptr
               float* __restrict__ hlast)         // [B][128] or nullptr
{
    __shared__ __align__(16) __half A[2][16 * 136];   // double-buffered h tile

    const int tid  = threadIdx.x;
    const int wid  = tid >> 5;
    const int lane = tid & 31;
    const int grp  = blockIdx.x >> 1;
    const uint32_t rank = blockIdx.x & 1;
    const uint32_t peer = rank ^ 1u;
    const int b0   = grp * NBC;
    const int nb   = (NB - b0 < NBC) ? (NB - b0) : NBC;

    const int gp  = lane >> 2;           // D-frag row (= batch row) 0..7
    const int tig = lane & 3;
    const int u   = (int)rank * 64 + wid * 4 + tig;   // owned global unit
    const bool vA = (gp < nb);
    const bool vB = (gp + 8 < nb);

    // warp's 2 n8 tiles (global tile idx)
    const int cb0 = (int)rank * 32 + wid * 2;
    const uint2* __restrict__ WRp = reinterpret_cast<const uint2*>(WR);

    uint2 breg[2][8];
#pragma unroll
    for (int nt = 0; nt < 2; ++nt)
#pragma unroll
        for (int ks = 0; ks < 8; ++ks)
            breg[nt][ks] = WRp[(size_t)((cb0 + nt) * 8 + ks) * 32 + lane];

    // zero both A buffers (h starts at 0; pad rows stay 0)
    for (int i = tid; i < 2 * 16 * 136 / 2; i += 512)
        reinterpret_cast<uint32_t*>(&A[0][0])[i] = 0u;
    CLUSTER_ARRIVE();
    CLUSTER_WAIT();

    const int lrow = (lane & 7) + ((lane >> 3) & 1) * 8;
    const int kadd = (lane >> 4) * 8;
    const uint32_t Ab0 = smem_u32(&A[0][0]);
    const uint32_t Ab1 = smem_u32(&A[1][0]);
    const unsigned FULL = 0xffffffffu;
    const int s0 = gp * 4 + 2 * (tig & 1);
    const int s1 = s0 + 1;
    const bool lowtile = (tig < 2);      // nt = tig>>1

    // preload xp for t=0
    uint2 xa = make_uint2(0u, 0u), xb = make_uint2(0u, 0u);
    if (vA) xa = *reinterpret_cast<const uint2*>(
        &xp[((size_t)(b0 + gp) * NT + 0) * 512 + u * 4]);
    if (vB) xb = *reinterpret_cast<const uint2*>(
        &xp[((size_t)(b0 + gp + 8) * NT + 0) * 512 + u * 4]);

    float cst[2] = {0.f, 0.f};
    int p = 0;

    for (int t = 0; t < NT; ++t) {
        // ---- W_hh * h via mma.sync, fp16 accumulators ----
        uint32_t acc[2][2];
#pragma unroll
        for (int nt = 0; nt < 2; ++nt) { acc[nt][0] = 0u; acc[nt][1] = 0u; }

        const uint32_t Ab = p ? Ab1 : Ab0;
#pragma unroll
        for (int ks = 0; ks < 8; ++ks) {
            uint32_t addr = Ab + (uint32_t)(lrow * 136 + ks * 16 + kadd) * 2;
            uint32_t a0, a1, a2, a3;
            asm volatile("ldmatrix.sync.aligned.m8n8.x4.shared.b16 {%0,%1,%2,%3}, [%4];"
                         : "=r"(a0), "=r"(a1), "=r"(a2), "=r"(a3) : "r"(addr));
#pragma unroll
            for (int nt = 0; nt < 2; ++nt) {
                asm volatile(
                    "mma.sync.aligned.m16n8k16.row.col.f16.f16.f16.f16 "
                    "{%0,%1}, {%2,%3,%4,%5}, {%6,%7}, {%0,%1};"
                    : "+r"(acc[nt][0]), "+r"(acc[nt][1])
                    : "r"(a0), "r"(a1), "r"(a2), "r"(a3),
                      "r"(breg[nt][ks].x), "r"(breg[nt][ks].y));
            }
        }

        // ---- shuffle redistribution: 2 cells (rows gp, gp+8) for unit u ----
        uint32_t e0 = __shfl_sync(FULL, acc[0][0], s0);
        uint32_t e1 = __shfl_sync(FULL, acc[0][0], s1);
        uint32_t f0 = __shfl_sync(FULL, acc[1][0], s0);
        uint32_t f1 = __shfl_sync(FULL, acc[1][0], s1);
        uint32_t qa01 = lowtile ? e0 : f0;
        uint32_t qa23 = lowtile ? e1 : f1;
        uint32_t g0 = __shfl_sync(FULL, acc[0][1], s0);
        uint32_t g1 = __shfl_sync(FULL, acc[0][1], s1);
        uint32_t h0 = __shfl_sync(FULL, acc[1][1], s0);
        uint32_t h1 = __shfl_sync(FULL, acc[1][1], s1);
        uint32_t qb01 = lowtile ? g0 : h0;
        uint32_t qb23 = lowtile ? g1 : h1;

        // ---- pointwise + h writes (local A, peer A via DSMEM, gmem) ----
        __half* An = p ? &A[0][0] : &A[1][0];
        const uint32_t Abn = p ? Ab0 : Ab1;

#pragma unroll
        for (int cell = 0; cell < 2; ++cell) {
            const int row = cell ? (gp + 8) : gp;
            uint32_t q01 = cell ? qb01 : qa01;
            uint32_t q23 = cell ? qb23 : qa23;
            uint2 xpu = cell ? xb : xa;
            float2 r01 = __half22float2(*reinterpret_cast<__half2*>(&q01));
            float2 r23 = __half22float2(*reinterpret_cast<__half2*>(&q23));
            float2 x01 = __half22float2(reinterpret_cast<const __half2*>(&xpu)[0]);
            float2 x23 = __half22float2(reinterpret_cast<const __half2*>(&xpu)[1]);
            float gi = r01.x + x01.x;
            float gf = r01.y + x01.y;
            float gg = r23.x + x23.x;
            float go = r23.y + x23.y;
            float ii = fast_sig(gi);
            float ff = fast_sig(gf);
            float gz = fast_tanh(gg);
            float oo = fast_sig(go);
            float cn = fmaf(ff, cst[cell], ii * gz);
            cst[cell] = cn;
            float hn = oo * fast_tanh(cn);
            __half hn16 = __float2half(hn);

            An[row * 136 + u] = hn16;
            st_peer_b16(Abn + (uint32_t)(row * 136 + u) * 2, peer, hn16);

            const bool vld = cell ? vB : vA;
            if (hout && vld)
                hout[((size_t)(b0 + row) * NT + t) * NH + u] = hn16;
            if (hlast && vld && t == NT - 1)
                hlast[(b0 + row) * NH + u] = hn;
        }

        CLUSTER_ARRIVE();

        // ---- prefetch xp for t+1 while the cluster barrier drains ----
        uint2 na = make_uint2(0u, 0u), nb2 = make_uint2(0u, 0u);
        if (t + 1 < NT) {
            if (vA) na = *reinterpret_cast<const uint2*>(
                &xp[((size_t)(b0 + gp) * NT + (t + 1)) * 512 + u * 4]);
            if (vB) nb2 = *reinterpret_cast<const uint2*>(
                &xp[((size_t)(b0 + gp + 8) * NT + (t + 1)) * 512 + u * 4]);
        }

        CLUSTER_WAIT();
        xa = na; xb = nb2;
        p ^= 1;
    }
}

// ---------------- final FC on last timestep of layer 2 ----------------
__global__ void fc_kernel(const float* __restrict__ fc_w,
                          const float* __restrict__ fc_b,
                          float* __restrict__ out)
{
    int b = blockIdx.x;
    int tid = threadIdx.x;
    float p = g_hlast[b * NH + tid] * fc_w[tid];
#pragma unroll
    for (int o = 16; o; o >>= 1) p += __shfl_down_sync(0xffffffffu, p, o);
    __shared__ float ws[4];
    if ((tid & 31) == 0) ws[tid >> 5] = p;
    __syncthreads();
    if (tid == 0) out[b] = ws[0] + ws[1] + ws[2] + ws[3] + fc_b[0];
}

// ---------------- launch ----------------
extern "C" void kernel_launch(void* const* d_in, const int* in_sizes, int n_in,
                              void* d_out, int out_size)
{
    const float* x    = (const float*)d_in[0];
    const float* wih0 = (const float*)d_in[1];
    const float* whh0 = (const float*)d_in[2];
    const float* bih0 = (const float*)d_in[3];
    const float* bhh0 = (const float*)d_in[4];
    const float* wih1 = (const float*)d_in[5];
    const float* whh1 = (const float*)d_in[6];
    const float* bih1 = (const float*)d_in[7];
    const float* bhh1 = (const float*)d_in[8];
    const float* wih2 = (const float*)d_in[9];
    const float* whh2 = (const float*)d_in[10];
    const float* bih2 = (const float*)d_in[11];
    const float* bhh2 = (const float*)d_in[12];
    const float* fcw  = (const float*)d_in[13];
    const float* fcb  = (const float*)d_in[14];
    float* out = (float*)d_out;

    void *ph0, *ph1, *phl, *pxp, *pwf, *pwr, *pbias, *pw0;
    cudaGetSymbolAddress(&ph0, g_h0);
    cudaGetSymbolAddress(&ph1, g_h1);
    cudaGetSymbolAddress(&phl, g_hlast);
    cudaGetSymbolAddress(&pxp, g_xph);
    cudaGetSymbolAddress(&pwf, g_WF);
    cudaGetSymbolAddress(&pwr, g_WR);
    cudaGetSymbolAddress(&pbias, g_biasxp);
    cudaGetSymbolAddress(&pw0, g_w0p);

    __half* h0   = (__half*)ph0;
    __half* h1   = (__half*)ph1;
    float*  hl   = (float*)phl;
    __half* xp   = (__half*)pxp;
    __half* WF   = (__half*)pwf;
    __half* WR   = (__half*)pwr;
    float*  bs   = (float*)pbias;
    float*  w0p  = (float*)pw0;

    const int rec_grid = 2 * ((NB + NBC - 1) / NBC);   // 2 * 74 = 148

    // prep
    prep_l0_kernel <<<64, 256>>>(wih0, bih0, bhh0, w0p, bs + 0 * 512);
    prep_mma_kernel<<<132, 256>>>(whh0, bih0, bhh0, WR + 0 * 65536, bs + 0 * 512);
    prep_mma_kernel<<<132, 256>>>(wih1, bih1, bhh1, WF + 0 * 65536, bs + 1 * 512);
    prep_mma_kernel<<<132, 256>>>(whh1, bih1, bhh1, WR + 1 * 65536, bs + 1 * 512);
    prep_mma_kernel<<<132, 256>>>(wih2, bih2, bhh2, WF + 1 * 65536, bs + 2 * 512);
    prep_mma_kernel<<<132, 256>>>(whh2, bih2, bhh2, WR + 2 * 65536, bs + 2 * 512);

    // layer 0
    xp0_kernel<<<BT / 128, 512>>>(x, w0p, bs + 0 * 512, xp);
    rec_mma_kernel<<<rec_grid, 512>>>(xp, WR + 0 * 65536, h0, nullptr);

    // layer 1
    {
        dim3 g(BT / 128, 2);
        xp_mma_kernel<<<g, 512>>>(h0, WF + 0 * 65536, bs + 1 * 512, xp);
    }
    rec_mma_kernel<<<rec_grid, 512>>>(xp, WR + 1 * 65536, h1, nullptr);

    // layer 2
    {
        dim3 g(BT / 128, 2);
        xp_mma_kernel<<<g, 512>>>(h1, WF + 1 * 65536, bs + 2 * 512, xp);
    }
    rec_mma_kernel<<<rec_grid, 512>>>(xp, WR + 2 * 65536, nullptr, hl);

    fc_kernel<<<NB, 128>>>(fcw, fcb, out);
}

// round 14
// speedup vs baseline: 1.2594x; 1.2594x over previous
#include <cuda_runtime.h>
#include <cuda_fp16.h>
#include <cstdint>
#include <cstddef>

#define NB 1024
#define NT 512
#define NH 128
#define BT (NB * NT)
#define NBC 7   // batches per rec CTA (one n8 tile, 1 pad col)

// ---------------- scratch (device globals; no runtime allocation) ----------------
__device__ __half g_h0[(size_t)NB * NT * NH];   // layer0 out fp16 [B][T][H]
__device__ __half g_h1[(size_t)NB * NT * NH];   // layer1 out fp16 [B][T][H]
__device__ float  g_hlast[NB * NH];             // layer2 last h (fp32)
__device__ __half g_xph[(size_t)BT * 512];      // x-projection fp16 (reused per layer)
__device__ __half g_WF[2][65536];               // mma B-frag packed w_ih (xp kernels)
__device__ __half g_WA[3][65536];               // mma A-frag packed w_hh (rec kernels)
__device__ float  g_biasxp[3][512];             // per-layer bias (c = u*4+q order)
__device__ float  g_w0p[512 * 8];               // layer0 w_ih packed [c][8] (k<6)

// ---------------- activations / helpers ----------------
__device__ __forceinline__ float fast_tanh(float x) {
    float y;
    asm("tanh.approx.f32 %0, %1;" : "=f"(y) : "f"(x));
    return y;
}
__device__ __forceinline__ float fast_sig(float x) {
    return fmaf(0.5f, fast_tanh(0.5f * x), 0.5f);
}
__device__ __forceinline__ uint32_t smem_u32(const void* p) {
    uint32_t a;
    asm("{ .reg .u64 t; cvta.to.shared.u64 t, %1; cvt.u32.u64 %0, t; }" : "=r"(a) : "l"(p));
    return a;
}

// ---------------- prep: xp-kernel B-frag pack ([512,128] w_ih) + bias ----------
__global__ void prep_mma_kernel(const float* __restrict__ W,
                                const float* __restrict__ b_ih,
                                const float* __restrict__ b_hh,
                                __half* __restrict__ WF, float* __restrict__ bias)
{
    for (int idx = blockIdx.x * blockDim.x + threadIdx.x; idx < 65536;
         idx += gridDim.x * blockDim.x) {
        int h4   = idx & 3;
        int lane = (idx >> 2) & 31;
        int ks   = (idx >> 7) & 7;
        int cb   = idx >> 10;
        int c = cb * 8 + (lane >> 2);
        int q = c & 3, u = c >> 2;
        int g = q * NH + u;
        int k = ks * 16 + (lane & 3) * 2 + (h4 & 1) + (h4 >> 1) * 8;
        WF[idx] = __float2half(W[g * NH + k]);
    }
    for (int c = blockIdx.x * blockDim.x + threadIdx.x; c < 512;
         c += gridDim.x * blockDim.x) {
        int q = c & 3, u = c >> 2;
        int g = q * NH + u;
        bias[c] = b_ih[g] + b_hh[g];
    }
}

// ---------------- prep: rec-kernel A-frag pack ([512,128] w_hh) ----------------
// flat half idx = ((((w*2+mt)*8+ks)*32+lane)*4+reg)*2+hh
// gate row q = mt*2 + (reg&1); unit u = w*8 + (lane>>2);
// k = ks*16 + (lane&3)*2 + (reg>>1)*8 + hh;  val = W[(q*128+u)*128 + k]
__global__ void prep_areg_kernel(const float* __restrict__ W, __half* __restrict__ WA)
{
    for (int idx = blockIdx.x * blockDim.x + threadIdx.x; idx < 65536;
         idx += gridDim.x * blockDim.x) {
        int hh   = idx & 1;
        int reg  = (idx >> 1) & 3;
        int lane = (idx >> 3) & 31;
        int ks   = (idx >> 8) & 7;
        int mt   = (idx >> 11) & 1;
        int w    = idx >> 12;
        int q = mt * 2 + (reg & 1);
        int u = w * 8 + (lane >> 2);
        int k = ks * 16 + (lane & 3) * 2 + ((reg >> 1) * 8) + hh;
        WA[idx] = __float2half(W[(q * NH + u) * NH + k]);
    }
}

// ---------------- prep: layer0 w_ih pack (K=6) + bias ----------------
__global__ void prep_l0_kernel(const float* __restrict__ w_ih,
                               const float* __restrict__ b_ih,
                               const float* __restrict__ b_hh,
                               float* __restrict__ w0p, float* __restrict__ bias)
{
    for (int idx = blockIdx.x * blockDim.x + threadIdx.x; idx < 512 * 8;
         idx += gridDim.x * blockDim.x) {
        int k = idx & 7, c = idx >> 3;
        int q = c & 3, u = c >> 2;
        int g = q * NH + u;
        w0p[idx] = (k < 6) ? w_ih[g * 6 + k] : 0.0f;
    }
    for (int c = blockIdx.x * blockDim.x + threadIdx.x; c < 512;
         c += gridDim.x * blockDim.x) {
        int q = c & 3, u = c >> 2;
        int g = q * NH + u;
        bias[c] = b_ih[g] + b_hh[g];
    }
}

// ---------------- layer0 x-projection (scalar, K=6) -> fp16 ----------------
__global__ void __launch_bounds__(512, 1)
xp0_kernel(const float* __restrict__ x, const float* __restrict__ w0p,
           const float* __restrict__ bias, __half* __restrict__ XP)
{
    __shared__ __align__(16) float xs[128 * 8];
    const int tid = threadIdx.x;
    const size_t row0 = (size_t)blockIdx.x * 128;

    for (int i = tid; i < 1024; i += 512) {
        int r = i >> 3, k = i & 7;
        xs[i] = (k < 6) ? x[(row0 + r) * 6 + k] : 0.0f;
    }
    __syncthreads();

    const int c = tid;
    float4 w01 = *reinterpret_cast<const float4*>(&w0p[c * 8]);
    float4 w23 = *reinterpret_cast<const float4*>(&w0p[c * 8 + 4]);
    float bc = bias[c];
    for (int r = 0; r < 128; ++r) {
        float4 x01 = *reinterpret_cast<const float4*>(&xs[r * 8]);
        float2 x2  = *reinterpret_cast<const float2*>(&xs[r * 8 + 4]);
        float s = bc;
        s = fmaf(w01.x, x01.x, s);
        s = fmaf(w01.y, x01.y, s);
        s = fmaf(w01.z, x01.z, s);
        s = fmaf(w01.w, x01.w, s);
        s = fmaf(w23.x, x2.x, s);
        s = fmaf(w23.y, x2.y, s);
        XP[(row0 + r) * 512 + c] = __float2half(s);
    }
}

// ---------------- layers 1,2 x-projection via mma.sync -> fp16 ----------------
__global__ void __launch_bounds__(512, 1)
xp_mma_kernel(const __half* __restrict__ X, const __half* __restrict__ WF,
              const float* __restrict__ bias, __half* __restrict__ XP)
{
    __shared__ __align__(16) __half xs[128 * 136];
    const int tid  = threadIdx.x;
    const int wid  = tid >> 5;
    const int lane = tid & 31;
    const size_t row0 = (size_t)blockIdx.x * 128;
    const int ny = blockIdx.y;

    for (int i = tid; i < 2048; i += 512) {
        int r = i >> 4, cvec = i & 15;
        reinterpret_cast<uint4*>(xs)[r * 17 + cvec] =
            reinterpret_cast<const uint4*>(X + (row0 + r) * NH)[cvec];
    }
    __syncthreads();

    const int wm = wid & 3;
    const int wn = wid >> 2;
    const int cb0 = ny * 32 + wn * 8;
    const uint2* __restrict__ WFp = reinterpret_cast<const uint2*>(WF);

    const int lrow = (lane & 7) + ((lane >> 3) & 1) * 8;
    const int kadd = (lane >> 4) * 8;
    const uint32_t xsb = smem_u32(xs);

    float acc[2][8][4];
#pragma unroll
    for (int mt = 0; mt < 2; ++mt)
#pragma unroll
        for (int nt = 0; nt < 8; ++nt)
#pragma unroll
            for (int i = 0; i < 4; ++i) acc[mt][nt][i] = 0.0f;

#pragma unroll
    for (int ks = 0; ks < 8; ++ks) {
        uint2 b[8];
#pragma unroll
        for (int nt = 0; nt < 8; ++nt)
            b[nt] = WFp[(size_t)((cb0 + nt) * 8 + ks) * 32 + lane];

#pragma unroll
        for (int mt = 0; mt < 2; ++mt) {
            int row = wm * 32 + mt * 16 + lrow;
            uint32_t addr = xsb + (uint32_t)(row * 136 + ks * 16 + kadd) * 2;
            uint32_t a0, a1, a2, a3;
            asm volatile("ldmatrix.sync.aligned.m8n8.x4.shared.b16 {%0,%1,%2,%3}, [%4];"
                         : "=r"(a0), "=r"(a1), "=r"(a2), "=r"(a3) : "r"(addr));
#pragma unroll
            for (int nt = 0; nt < 8; ++nt) {
                asm volatile(
                    "mma.sync.aligned.m16n8k16.row.col.f32.f16.f16.f32 "
                    "{%0,%1,%2,%3}, {%4,%5,%6,%7}, {%8,%9}, {%0,%1,%2,%3};"
                    : "+f"(acc[mt][nt][0]), "+f"(acc[mt][nt][1]),
                      "+f"(acc[mt][nt][2]), "+f"(acc[mt][nt][3])
                    : "r"(a0), "r"(a1), "r"(a2), "r"(a3),
                      "r"(b[nt].x), "r"(b[nt].y));
            }
        }
    }

    const int gp = lane >> 2, tig = lane & 3;
#pragma unroll
    for (int mt = 0; mt < 2; ++mt) {
#pragma unroll
        for (int nt = 0; nt < 8; ++nt) {
            size_t row = row0 + wm * 32 + mt * 16 + gp;
            int col = ny * 256 + wn * 64 + nt * 8 + tig * 2;
            float2 bb = *reinterpret_cast<const float2*>(&bias[col]);
            __half2 o0 = __floats2half2_rn(acc[mt][nt][0] + bb.x, acc[mt][nt][1] + bb.y);
            __half2 o1 = __floats2half2_rn(acc[mt][nt][2] + bb.x, acc[mt][nt][3] + bb.y);
            *reinterpret_cast<__half2*>(&XP[row * 512 + col]) = o0;
            *reinterpret_cast<__half2*>(&XP[(row + 8) * 512 + col]) = o1;
        }
    }
}

// ---------------- recurrent LSTM layer: gates-on-M mma.sync ----------------
// 147 CTAs x 512 thr; CTA = 7 batches on the n8 dimension (1 pad col).
// Warp w owns units u = w*8 + gp via 2 m16 tiles: mtile0 = gates {i,f},
// mtile1 = {g,o}. A-frags (w_hh) loop-invariant in 64 regs; B = h tile in
// smem [8 batch][136 unit], read with 2 conflict-free LDS.32 per k-step.
// Each thread's 8 fp32 accs hold complete gate quads for cells (u, 2tig)
// and (u, 2tig+1): NO shuffles, NO smem D. One sync/step; xp prefetched
// one full step ahead.
__global__ void __launch_bounds__(512, 1)
rec_mma_kernel(const __half* __restrict__ xp,     // [BT][512] fp16, bias included
               const __half* __restrict__ WA,     // A-frag packed w_hh
               __half* __restrict__ hout,         // [B][T][128] or nullptr
               float* __restrict__ hlast)         // [B][128] or nullptr
{
    __shared__ __align__(16) __half Bt[2][8 * 136];   // double-buffered h tile

    const int tid  = threadIdx.x;
    const int wid  = tid >> 5;
    const int lane = tid & 31;
    const int bc0  = blockIdx.x * NBC;
    const int nb   = (NB - bc0 < NBC) ? (NB - bc0) : NBC;

    const int gp  = lane >> 2;
    const int tig = lane & 3;
    const int u   = wid * 8 + gp;        // owned unit
    const int b0  = 2 * tig;             // owned batch cols
    const int b1  = 2 * tig + 1;
    const bool v0 = (b0 < nb);
    const bool v1 = (b1 < nb);

    // loop-invariant A fragments (w_hh): 2 mtiles x 8 ksteps x uint4 = 64 regs
    uint4 areg[2][8];
    const uint4* WA4 = reinterpret_cast<const uint4*>(WA + (size_t)wid * 4096);
#pragma unroll
    for (int mt = 0; mt < 2; ++mt)
#pragma unroll
        for (int ks = 0; ks < 8; ++ks)
            areg[mt][ks] = WA4[(mt * 8 + ks) * 32 + lane];

    // zero both B buffers (h starts at 0; pad col stays bounded)
    for (int i = tid; i < 2 * 8 * 136 / 2; i += 512)
        reinterpret_cast<uint32_t*>(&Bt[0][0])[i] = 0u;
    __syncthreads();

    // preload xp for t=0
    uint2 xa = make_uint2(0u, 0u), xb = make_uint2(0u, 0u);
    if (v0) xa = *reinterpret_cast<const uint2*>(
        &xp[((size_t)(bc0 + b0) * NT + 0) * 512 + u * 4]);
    if (v1) xb = *reinterpret_cast<const uint2*>(
        &xp[((size_t)(bc0 + b1) * NT + 0) * 512 + u * 4]);

    float cst[2] = {0.f, 0.f};
    int p = 0;

    for (int t = 0; t < NT; ++t) {
        // ---- prefetch xp for t+1 (consumed next iteration) ----
        uint2 na = make_uint2(0u, 0u), nbq = make_uint2(0u, 0u);
        if (t + 1 < NT) {
            if (v0) na = *reinterpret_cast<const uint2*>(
                &xp[((size_t)(bc0 + b0) * NT + (t + 1)) * 512 + u * 4]);
            if (v1) nbq = *reinterpret_cast<const uint2*>(
                &xp[((size_t)(bc0 + b1) * NT + (t + 1)) * 512 + u * 4]);
        }

        // ---- W_hh * h: 16 mma, B-frags via 2 LDS.32 per k-step ----
        float acc[2][4];
#pragma unroll
        for (int mt = 0; mt < 2; ++mt)
#pragma unroll
            for (int i = 0; i < 4; ++i) acc[mt][i] = 0.0f;

        const char* Bp = reinterpret_cast<const char*>(&Bt[p][0]);
#pragma unroll
        for (int ks = 0; ks < 8; ++ks) {
            uint32_t bb0 = *reinterpret_cast<const uint32_t*>(
                Bp + gp * 272 + ks * 32 + tig * 4);
            uint32_t bb1 = *reinterpret_cast<const uint32_t*>(
                Bp + gp * 272 + ks * 32 + tig * 4 + 16);
#pragma unroll
            for (int mt = 0; mt < 2; ++mt) {
                asm volatile(
                    "mma.sync.aligned.m16n8k16.row.col.f32.f16.f16.f32 "
                    "{%0,%1,%2,%3}, {%4,%5,%6,%7}, {%8,%9}, {%0,%1,%2,%3};"
                    : "+f"(acc[mt][0]), "+f"(acc[mt][1]),
                      "+f"(acc[mt][2]), "+f"(acc[mt][3])
                    : "r"(areg[mt][ks].x), "r"(areg[mt][ks].y),
                      "r"(areg[mt][ks].z), "r"(areg[mt][ks].w),
                      "r"(bb0), "r"(bb1));
            }
        }

        // ---- pointwise: 2 complete cells from own registers ----
        __half* Bn = &Bt[1 - p][0];
#pragma unroll
        for (int cell = 0; cell < 2; ++cell) {
            const int b = cell ? b1 : b0;
            const uint2 xpu = cell ? xb : xa;
            float2 x01 = __half22float2(reinterpret_cast<const __half2*>(&xpu)[0]);
            float2 x23 = __half22float2(reinterpret_cast<const __half2*>(&xpu)[1]);
            float gi = acc[0][0 + cell] + x01.x;   // row gp   of mtile0 = gate i
            float gf = acc[0][2 + cell] + x01.y;   // row gp+8 of mtile0 = gate f
            float gg = acc[1][0 + cell] + x23.x;   // row gp   of mtile1 = gate g
            float go = acc[1][2 + cell] + x23.y;   // row gp+8 of mtile1 = gate o
            float ii = fast_sig(gi);
            float ff = fast_sig(gf);
            float gz = fast_tanh(gg);
            float oo = fast_sig(go);
            float cn = fmaf(ff, cst[cell], ii * gz);
            cst[cell] = cn;
            float hn = oo * fast_tanh(cn);
            __half hn16 = __float2half(hn);

            Bn[b * 136 + u] = hn16;
            const bool vld = cell ? v1 : v0;
            if (hout && vld)
                hout[((size_t)(bc0 + b) * NT + t) * NH + u] = hn16;
            if (hlast && vld && t == NT - 1)
                hlast[(bc0 + b) * NH + u] = hn;
        }

        xa = na; xb = nbq;
        __syncthreads();
        p ^= 1;
    }
}

// ---------------- final FC on last timestep of layer 2 ----------------
__global__ void fc_kernel(const float* __restrict__ fc_w,
                          const float* __restrict__ fc_b,
                          float* __restrict__ out)
{
    int b = blockIdx.x;
    int tid = threadIdx.x;
    float p = g_hlast[b * NH + tid] * fc_w[tid];
#pragma unroll
    for (int o = 16; o; o >>= 1) p += __shfl_down_sync(0xffffffffu, p, o);
    __shared__ float ws[4];
    if ((tid & 31) == 0) ws[tid >> 5] = p;
    __syncthreads();
    if (tid == 0) out[b] = ws[0] + ws[1] + ws[2] + ws[3] + fc_b[0];
}

// ---------------- launch ----------------
extern "C" void kernel_launch(void* const* d_in, const int* in_sizes, int n_in,
                              void* d_out, int out_size)
{
    const float* x    = (const float*)d_in[0];
    const float* wih0 = (const float*)d_in[1];
    const float* whh0 = (const float*)d_in[2];
    const float* bih0 = (const float*)d_in[3];
    const float* bhh0 = (const float*)d_in[4];
    const float* wih1 = (const float*)d_in[5];
    const float* whh1 = (const float*)d_in[6];
    const float* bih1 = (const float*)d_in[7];
    const float* bhh1 = (const float*)d_in[8];
    const float* wih2 = (const float*)d_in[9];
    const float* whh2 = (const float*)d_in[10];
    const float* bih2 = (const float*)d_in[11];
    const float* bhh2 = (const float*)d_in[12];
    const float* fcw  = (const float*)d_in[13];
    const float* fcb  = (const float*)d_in[14];
    float* out = (float*)d_out;

    void *ph0, *ph1, *phl, *pxp, *pwf, *pwa, *pbias, *pw0;
    cudaGetSymbolAddress(&ph0, g_h0);
    cudaGetSymbolAddress(&ph1, g_h1);
    cudaGetSymbolAddress(&phl, g_hlast);
    cudaGetSymbolAddress(&pxp, g_xph);
    cudaGetSymbolAddress(&pwf, g_WF);
    cudaGetSymbolAddress(&pwa, g_WA);
    cudaGetSymbolAddress(&pbias, g_biasxp);
    cudaGetSymbolAddress(&pw0, g_w0p);

    __half* h0   = (__half*)ph0;
    __half* h1   = (__half*)ph1;
    float*  hl   = (float*)phl;
    __half* xp   = (__half*)pxp;
    __half* WF   = (__half*)pwf;
    __half* WA   = (__half*)pwa;
    float*  bs   = (float*)pbias;
    float*  w0p  = (float*)pw0;

    const int rec_grid = (NB + NBC - 1) / NBC;   // 147

    // prep
    prep_l0_kernel  <<<64, 256>>>(wih0, bih0, bhh0, w0p, bs + 0 * 512);
    prep_areg_kernel<<<132, 256>>>(whh0, WA + 0 * 65536);
    prep_mma_kernel <<<132, 256>>>(wih1, bih1, bhh1, WF + 0 * 65536, bs + 1 * 512);
    prep_areg_kernel<<<132, 256>>>(whh1, WA + 1 * 65536);
    prep_mma_kernel <<<132, 256>>>(wih2, bih2, bhh2, WF + 1 * 65536, bs + 2 * 512);
    prep_areg_kernel<<<132, 256>>>(whh2, WA + 2 * 65536);

    // layer 0
    xp0_kernel<<<BT / 128, 512>>>(x, w0p, bs + 0 * 512, xp);
    rec_mma_kernel<<<rec_grid, 512>>>(xp, WA + 0 * 65536, h0, nullptr);

    // layer 1
    {
        dim3 g(BT / 128, 2);
        xp_mma_kernel<<<g, 512>>>(h0, WF + 0 * 65536, bs + 1 * 512, xp);
    }
    rec_mma_kernel<<<rec_grid, 512>>>(xp, WA + 1 * 65536, h1, nullptr);

    // layer 2
    {
        dim3 g(BT / 128, 2);
        xp_mma_kernel<<<g, 512>>>(h1, WF + 1 * 65536, bs + 2 * 512, xp);
    }
    rec_mma_kernel<<<rec_grid, 512>>>(xp, WA + 2 * 65536, nullptr, hl);

    fc_kernel<<<NB, 128>>>(fcw, fcb, out);
}